// round 4
// baseline (speedup 1.0000x reference)
#include <cuda_runtime.h>

typedef unsigned long long u64;

#define NFLOWS 8
#define HID 64

// ---------------------------------------------------------------------------
// Precomputed per-launch constants (written by prep kernels, read by main).
// __device__ globals only — no allocations anywhere (harness rule).
// ---------------------------------------------------------------------------
struct Pre {
    float L[9];        // cholesky(Lt Lt^T), row-major lower
    float bm[3];       // base mean
    float totc;        // sum over flows of (sum ls + sum lls)
    float Wc[NFLOWS][9];  // folded (P l U) * diag(exp(ls))
    float c[NFLOWS][3];   // Wc @ shift
};
__device__ Pre g_pre;
__device__ float g_W2T[NFLOWS * HID * HID];   // W2 transposed: [f][k][j]

// ---------------------------------------------------------------------------
// Packed fp32x2 helpers (Blackwell FFMA2 path — only reachable via PTX)
// ---------------------------------------------------------------------------
__device__ __forceinline__ u64 pk2(float lo, float hi) {
    u64 r; asm("mov.b64 %0,{%1,%2};" : "=l"(r) : "f"(lo), "f"(hi)); return r;
}
__device__ __forceinline__ void upk2(u64 v, float& lo, float& hi) {
    asm("mov.b64 {%0,%1},%2;" : "=f"(lo), "=f"(hi) : "l"(v));
}
__device__ __forceinline__ u64 fma2(u64 a, u64 b, u64 c) {
    u64 d; asm("fma.rn.f32x2 %0,%1,%2,%3;" : "=l"(d) : "l"(a), "l"(b), "l"(c)); return d;
}
__device__ __forceinline__ float red2(u64 v) {
    float lo, hi; upk2(v, lo, hi); return lo + hi;
}
__device__ __forceinline__ u64 relu2(u64 v) {
    float lo, hi; upk2(v, lo, hi);
    return pk2(fmaxf(lo, 0.f), fmaxf(hi, 0.f));
}

// ---------------------------------------------------------------------------
// Prep kernel 1: 3x3 math (cholesky, folded flow matrices, log-det constant)
// ---------------------------------------------------------------------------
__global__ void prep_math(const float* __restrict__ L_tril, const float* __restrict__ bm,
                          const float* __restrict__ ls, const float* __restrict__ sh,
                          const float* __restrict__ P,  const float* __restrict__ ss,
                          const float* __restrict__ lm, const float* __restrict__ um,
                          const float* __restrict__ lls) {
    if (threadIdx.x != 0 || blockIdx.x != 0) return;

    float Lt[3][3], cov[3][3];
    for (int a = 0; a < 3; a++)
        for (int b = 0; b < 3; b++)
            Lt[a][b] = (b <= a ? L_tril[a * 3 + b] : 0.f) + (a == b ? 1e-6f : 0.f);
    for (int a = 0; a < 3; a++)
        for (int b = 0; b < 3; b++) {
            float s = 0.f;
            for (int k = 0; k < 3; k++) s += Lt[a][k] * Lt[b][k];
            cov[a][b] = s;
        }
    float L00 = sqrtf(cov[0][0]);
    float L10 = cov[1][0] / L00, L20 = cov[2][0] / L00;
    float L11 = sqrtf(cov[1][1] - L10 * L10);
    float L21 = (cov[2][1] - L20 * L10) / L11;
    float L22 = sqrtf(cov[2][2] - L20 * L20 - L21 * L21);
    float Lm[9] = {L00, 0.f, 0.f, L10, L11, 0.f, L20, L21, L22};
    for (int t = 0; t < 9; t++) g_pre.L[t] = Lm[t];
    for (int t = 0; t < 3; t++) g_pre.bm[t] = bm[t];

    float totc = 0.f;
    for (int f = 0; f < NFLOWS; f++) {
        float el[3], shv[3];
        for (int d = 0; d < 3; d++) {
            el[d] = expf(ls[f * 3 + d]);
            totc += ls[f * 3 + d] + lls[f * 3 + d];
            shv[d] = sh[f * 3 + d];
        }
        float l[3][3], U[3][3];
        for (int a = 0; a < 3; a++)
            for (int b = 0; b < 3; b++) {
                l[a][b] = (b < a ? lm[f * 9 + a * 3 + b] : (a == b ? 1.f : 0.f));
                U[a][b] = (b > a ? um[f * 9 + a * 3 + b] : 0.f);
            }
        for (int d = 0; d < 3; d++) U[d][d] = ss[f * 3 + d] * expf(lls[f * 3 + d]);

        float A[3][3], Wm[3][3];
        for (int a = 0; a < 3; a++)
            for (int b = 0; b < 3; b++) {
                float s = 0.f;
                for (int k = 0; k < 3; k++) s += l[a][k] * U[k][b];
                A[a][b] = s;
            }
        for (int a = 0; a < 3; a++)
            for (int b = 0; b < 3; b++) {
                float s = 0.f;
                for (int k = 0; k < 3; k++) s += P[f * 9 + a * 3 + k] * A[k][b];
                Wm[a][b] = s;
            }
        for (int a = 0; a < 3; a++) {
            float cs = 0.f;
            for (int b = 0; b < 3; b++) {
                float wc = Wm[a][b] * el[b];
                g_pre.Wc[f][a * 3 + b] = wc;
                cs += wc * shv[b];
            }
            g_pre.c[f][a] = cs;
        }
    }
    g_pre.totc = totc;
}

// ---------------------------------------------------------------------------
// Prep kernel 2: transpose W2 so hidden-layer weights are j-contiguous
// g_W2T[f][k][j] = W2[f][j][k]
// ---------------------------------------------------------------------------
__global__ void prep_transpose(const float* __restrict__ W2) {
    int idx = blockIdx.x * blockDim.x + threadIdx.x;
    if (idx < NFLOWS * HID * HID) {
        int f = idx >> 12;
        int k = (idx >> 6) & 63;
        int j = idx & 63;
        g_W2T[idx] = W2[f * 4096 + j * 64 + k];
    }
}

// ---------------------------------------------------------------------------
// Main kernel: one sample per thread, 128 threads / CTA
// Dynamic smem layout (floats):
// ---------------------------------------------------------------------------
#define OFF_W2T   0        // 4096 : current flow's W2^T
#define OFF_H     4096     // 8192 : per-thread h1 activations, [k][tid]
#define OFF_W1    12288    // 64
#define OFF_B1    12352    // 64
#define OFF_B2    12416    // 64
#define OFF_W3    12480    // 256
#define OFF_B3    12736    // 4 (+4 pad)
#define OFF_MISC  12744    // 12 (+ pad)
#define SMEM_FLOATS 12768
#define SMEM_BYTES (SMEM_FLOATS * 4)

__global__ __launch_bounds__(128)
void glow_main(const float* __restrict__ eps,
               const float* __restrict__ W1g, const float* __restrict__ b1g,
               const float* __restrict__ b2g,
               const float* __restrict__ W3g, const float* __restrict__ b3g,
               float* __restrict__ out, int N) {
    extern __shared__ float sm[];
    float* s_W2T  = sm + OFF_W2T;
    float* s_h    = sm + OFF_H;
    float* s_W1   = sm + OFF_W1;
    float* s_b1   = sm + OFF_B1;
    float* s_b2   = sm + OFF_B2;
    float* s_W3   = sm + OFF_W3;
    float* s_b3   = sm + OFF_B3;
    float* s_misc = sm + OFF_MISC;

    const int tid = threadIdx.x;
    const int gi  = blockIdx.x * 128 + tid;
    const bool valid = (gi < N);
    const int i = valid ? gi : (N - 1);

    // z = base_mean + eps @ L^T  (L lower triangular)
    float e0 = eps[3 * i + 0], e1 = eps[3 * i + 1], e2 = eps[3 * i + 2];
    float z0 = g_pre.bm[0] + g_pre.L[0] * e0;
    float z1 = g_pre.bm[1] + g_pre.L[3] * e0 + g_pre.L[4] * e1;
    float z2 = g_pre.bm[2] + g_pre.L[6] * e0 + g_pre.L[7] * e1 + g_pre.L[8] * e2;
    float ld = 0.f;

    for (int f = 0; f < NFLOWS; ++f) {
        __syncthreads();   // protect smem from previous flow's readers
        // ---- stage this flow's weights into smem ----
        {
            const float4* src = (const float4*)(g_W2T + f * 4096);
            float4* dst = (float4*)s_W2T;
            #pragma unroll
            for (int t = 0; t < 8; ++t) dst[tid + t * 128] = src[tid + t * 128];
            if (tid < 16)        ((float4*)s_W1)[tid]      = ((const float4*)(W1g + f * 64))[tid];
            else if (tid < 32)   ((float4*)s_b1)[tid - 16] = ((const float4*)(b1g + f * 64))[tid - 16];
            else if (tid < 48)   ((float4*)s_b2)[tid - 32] = ((const float4*)(b2g + f * 64))[tid - 32];
            else if (tid < 112)  ((float4*)s_W3)[tid - 48] = ((const float4*)(W3g + f * 256))[tid - 48];
            else if (tid == 112) ((float4*)s_b3)[0]        = ((const float4*)(b3g + f * 4))[0];
            if (tid < 9)         s_misc[tid] = g_pre.Wc[f][tid];
            else if (tid < 12)   s_misc[tid] = g_pre.c[f][tid - 9];
        }
        __syncthreads();

        // ---- folded actnorm + invertible 1x1 conv: z <- Wc z + c ----
        float n0 = s_misc[9]  + s_misc[0] * z0 + s_misc[1] * z1 + s_misc[2] * z2;
        float n1 = s_misc[10] + s_misc[3] * z0 + s_misc[4] * z1 + s_misc[5] * z2;
        float n2 = s_misc[11] + s_misc[6] * z0 + s_misc[7] * z1 + s_misc[8] * z2;
        z0 = n0; z1 = n1; z2 = n2;

        // ---- layer 1: h1[k] = relu(W1[k]*z0 + b1[k]) -> smem [k][tid] ----
        // (each thread only ever touches its own column; no barrier needed)
        #pragma unroll 8
        for (int k = 0; k < 64; ++k)
            s_h[k * 128 + tid] = fmaxf(fmaf(s_W1[k], z0, s_b1[k]), 0.f);

        // ---- layer 2: 64x64, output-pair-packed f32x2 accumulators ----
        u64 hn[32];
        const u64* b2u = (const u64*)s_b2;
        #pragma unroll
        for (int jp = 0; jp < 32; ++jp) hn[jp] = b2u[jp];

        #pragma unroll 2
        for (int k = 0; k < 64; ++k) {
            float hk = s_h[k * 128 + tid];
            u64 hb = pk2(hk, hk);
            const ulonglong2* wr = (const ulonglong2*)(s_W2T + k * 64);  // row k of W2^T
            #pragma unroll
            for (int q = 0; q < 16; ++q) {
                ulonglong2 w = wr[q];                       // broadcast LDS.128
                hn[2 * q]     = fma2(hb, w.x, hn[2 * q]);
                hn[2 * q + 1] = fma2(hb, w.y, hn[2 * q + 1]);
            }
        }
        #pragma unroll
        for (int jp = 0; jp < 32; ++jp) hn[jp] = relu2(hn[jp]);

        // ---- layer 3: 4x64, k-pair-packed ----
        float o[4];
        #pragma unroll
        for (int r = 0; r < 4; ++r) {
            const u64* w3r = (const u64*)(s_W3 + r * 64);
            u64 a0 = 0ull, a1 = 0ull;
            #pragma unroll
            for (int jp = 0; jp < 32; jp += 2) {
                a0 = fma2(hn[jp],     w3r[jp],     a0);
                a1 = fma2(hn[jp + 1], w3r[jp + 1], a1);
            }
            o[r] = red2(a0) + red2(a1) + s_b3[r];
        }

        // ---- affine coupling on (z1, z2) ----
        z1 = fmaf(z1, __expf(o[2]), o[0]);
        z2 = fmaf(z2, __expf(o[3]), o[1]);
        ld += o[2] + o[3];
    }

    if (valid) {
        float ldo = ld + g_pre.totc + z1 + z2;   // + z[:,1] + z[:,2] (pre-exp)
        out[3 * i + 0] = z0;
        out[3 * i + 1] = __expf(z1);
        out[3 * i + 2] = __expf(z2);
        out[3 * N + i] = ldo;
    }
}

// ---------------------------------------------------------------------------
// Launch. Input order (metadata): eps, L_tril, base_mean, an_log_scale,
// an_shift, perm_p, sign_s, lu_l, lu_u, lu_log_s, W1, b1, W2, b2, W3, b3
// Output: [z_t (N,3) row-major][log_det (N)] float32
// ---------------------------------------------------------------------------
extern "C" void kernel_launch(void* const* d_in, const int* in_sizes, int n_in,
                              void* d_out, int out_size) {
    const float* eps    = (const float*)d_in[0];
    const float* L_tril = (const float*)d_in[1];
    const float* bm     = (const float*)d_in[2];
    const float* an_ls  = (const float*)d_in[3];
    const float* an_sh  = (const float*)d_in[4];
    const float* perm   = (const float*)d_in[5];
    const float* ss     = (const float*)d_in[6];
    const float* lu_l   = (const float*)d_in[7];
    const float* lu_u   = (const float*)d_in[8];
    const float* lu_ls  = (const float*)d_in[9];
    const float* W1     = (const float*)d_in[10];
    const float* b1     = (const float*)d_in[11];
    const float* W2     = (const float*)d_in[12];
    const float* b2     = (const float*)d_in[13];
    const float* W3     = (const float*)d_in[14];
    const float* b3     = (const float*)d_in[15];
    float* out = (float*)d_out;

    int N = in_sizes[0] / 3;

    prep_math<<<1, 1>>>(L_tril, bm, an_ls, an_sh, perm, ss, lu_l, lu_u, lu_ls);
    prep_transpose<<<(NFLOWS * HID * HID + 255) / 256, 256>>>(W2);

    cudaFuncSetAttribute(glow_main, cudaFuncAttributeMaxDynamicSharedMemorySize, SMEM_BYTES);
    int blocks = (N + 127) / 128;
    glow_main<<<blocks, 128, SMEM_BYTES>>>(eps, W1, b1, b2, W3, b3, out, N);
}

// round 5
// speedup vs baseline: 6.2225x; 6.2225x over previous
#include <cuda_runtime.h>
#include <math_constants.h>

typedef unsigned long long u64;

#define NFLOWS 8
#define HID 64
#define NSEG 65

// ---------------------------------------------------------------------------
// Precomputed constants — __device__ globals only (no allocations, harness rule)
// ---------------------------------------------------------------------------
struct Pre {
    float L[9];           // cholesky(Lt Lt^T)
    float bm[3];          // base mean
    float totc;           // sum over flows of (sum ls + sum lls)
    float Wc[NFLOWS][9];  // folded (P l U) * diag(exp(ls))
    float c[NFLOWS][3];   // Wc @ shift
};
__device__ Pre g_pre;

// Per-flow blob staged into smem by the main kernel. 34624 bytes = 2164 float4.
struct FlowBlob {
    float  thr[64];         // sorted layer-1 breakpoints (+INF pads)
    float2 PQ[64 * NSEG];   // [u][s]: g_u(x) = P*x + Q on segment s
    float  w3t[64 * 4];     // [u][r]: W3[r][u]
    float  wc[9];           // folded 1x1-conv matrix
    float  c[3];            // folded conv bias
    float  b3[4];           // output bias
};
__device__ FlowBlob g_blob[NFLOWS];

#define BLOB_F4 (sizeof(FlowBlob) / 16)   // 2164

// ---------------------------------------------------------------------------
// Packed fp32x2 helpers (Blackwell FFMA2 — only reachable via PTX)
// ---------------------------------------------------------------------------
__device__ __forceinline__ u64 pk2(float lo, float hi) {
    u64 r; asm("mov.b64 %0,{%1,%2};" : "=l"(r) : "f"(lo), "f"(hi)); return r;
}
__device__ __forceinline__ void upk2(u64 v, float& lo, float& hi) {
    asm("mov.b64 {%0,%1},%2;" : "=f"(lo), "=f"(hi) : "l"(v));
}
__device__ __forceinline__ u64 fma2(u64 a, u64 b, u64 c) {
    u64 d; asm("fma.rn.f32x2 %0,%1,%2,%3;" : "=l"(d) : "l"(a), "l"(b), "l"(c)); return d;
}

// ---------------------------------------------------------------------------
// Prep 1: 3x3 math — cholesky + folded per-flow conv matrices (32 threads)
// ---------------------------------------------------------------------------
__global__ void prep_math(const float* __restrict__ L_tril, const float* __restrict__ bm,
                          const float* __restrict__ ls, const float* __restrict__ sh,
                          const float* __restrict__ P,  const float* __restrict__ ss,
                          const float* __restrict__ lm, const float* __restrict__ um,
                          const float* __restrict__ lls) {
    __shared__ float s_tot[8];
    int t = threadIdx.x;

    if (t == 0) {
        float Lt[3][3], cov[3][3];
        for (int a = 0; a < 3; a++)
            for (int b = 0; b < 3; b++)
                Lt[a][b] = (b <= a ? L_tril[a * 3 + b] : 0.f) + (a == b ? 1e-6f : 0.f);
        for (int a = 0; a < 3; a++)
            for (int b = 0; b < 3; b++) {
                float s = 0.f;
                for (int k = 0; k < 3; k++) s += Lt[a][k] * Lt[b][k];
                cov[a][b] = s;
            }
        float L00 = sqrtf(cov[0][0]);
        float L10 = cov[1][0] / L00, L20 = cov[2][0] / L00;
        float L11 = sqrtf(cov[1][1] - L10 * L10);
        float L21 = (cov[2][1] - L20 * L10) / L11;
        float L22 = sqrtf(cov[2][2] - L20 * L20 - L21 * L21);
        float Lm[9] = {L00, 0.f, 0.f, L10, L11, 0.f, L20, L21, L22};
        for (int q = 0; q < 9; q++) g_pre.L[q] = Lm[q];
        for (int q = 0; q < 3; q++) g_pre.bm[q] = bm[q];
    }

    if (t < 8) {
        int f = t;
        float tot = 0.f, el[3], shv[3];
        for (int d = 0; d < 3; d++) {
            el[d] = expf(ls[f * 3 + d]);
            tot += ls[f * 3 + d] + lls[f * 3 + d];
            shv[d] = sh[f * 3 + d];
        }
        float l[3][3], U[3][3];
        for (int a = 0; a < 3; a++)
            for (int b = 0; b < 3; b++) {
                l[a][b] = (b < a ? lm[f * 9 + a * 3 + b] : (a == b ? 1.f : 0.f));
                U[a][b] = (b > a ? um[f * 9 + a * 3 + b] : 0.f);
            }
        for (int d = 0; d < 3; d++) U[d][d] = ss[f * 3 + d] * expf(lls[f * 3 + d]);

        float A[3][3], Wm[3][3];
        for (int a = 0; a < 3; a++)
            for (int b = 0; b < 3; b++) {
                float s = 0.f;
                for (int k = 0; k < 3; k++) s += l[a][k] * U[k][b];
                A[a][b] = s;
            }
        for (int a = 0; a < 3; a++)
            for (int b = 0; b < 3; b++) {
                float s = 0.f;
                for (int k = 0; k < 3; k++) s += P[f * 9 + a * 3 + k] * A[k][b];
                Wm[a][b] = s;
            }
        for (int a = 0; a < 3; a++) {
            float cs = 0.f;
            for (int b = 0; b < 3; b++) {
                float wcv = Wm[a][b] * el[b];
                g_pre.Wc[f][a * 3 + b] = wcv;
                cs += wcv * shv[b];
            }
            g_pre.c[f][a] = cs;
        }
        s_tot[f] = tot;
    }
    __syncthreads();
    if (t == 0) {
        float s = 0.f;
        for (int f = 0; f < 8; f++) s += s_tot[f];
        g_pre.totc = s;
    }
}

// ---------------------------------------------------------------------------
// Prep 2: build piecewise-linear tables. 8 blocks (one per flow) x 64 threads.
//   thr: sorted breakpoints t_k = -b1_k/W1_k  (W1_k==0 -> +INF, never crossed)
//   PQ[u][s]: prefix-summed (P,Q) s.t. layer2 preact g_u(x) = P x + Q on seg s
// ---------------------------------------------------------------------------
__global__ void prep_build(const float* __restrict__ W1, const float* __restrict__ b1,
                           const float* __restrict__ W2, const float* __restrict__ b2,
                           const float* __restrict__ W3, const float* __restrict__ b3) {
    __shared__ float s_a[64], s_b[64], s_t[64], s_sorted[64];
    __shared__ int   s_ord[64];
    int f = blockIdx.x;
    int k = threadIdx.x;

    float a = W1[f * 64 + k];
    float b = b1[f * 64 + k];
    float tk = (a != 0.f) ? (-b / a) : CUDART_INF_F;
    s_a[k] = a; s_b[k] = b; s_t[k] = tk;
    __syncthreads();

    // rank sort (ties broken by index; INF==INF handled the same way)
    int r = 0;
    for (int j = 0; j < 64; ++j) {
        float tj = s_t[j];
        r += (tj < tk) || (tj == tk && j < k);
    }
    s_sorted[r] = tk; s_ord[r] = k;
    __syncthreads();

    FlowBlob* bl = &g_blob[f];
    bl->thr[k] = s_sorted[k];

    // active-set walk for unit u = k (double accumulation for exactness)
    const float* W2row = W2 + f * 4096 + k * 64;   // W2[f][u][:]
    double Pd = 0.0, Qd = (double)b2[f * 64 + k];
    for (int j = 0; j < 64; ++j) {
        // active as x -> -inf: a<0 (relu -> +inf side) or constant-positive unit
        if (s_a[j] < 0.f || (s_a[j] == 0.f && s_b[j] > 0.f)) {
            double w = (double)W2row[j];
            Pd += w * (double)s_a[j];
            Qd += w * (double)s_b[j];
        }
    }
    bl->PQ[k * NSEG + 0] = make_float2((float)Pd, (float)Qd);
    for (int s = 1; s <= 64; ++s) {
        int j = s_ord[s - 1];
        float aj = s_a[j];
        double w = (double)W2row[j];
        if (aj > 0.f)      { Pd += w * (double)aj; Qd += w * (double)s_b[j]; }
        else if (aj < 0.f) { Pd -= w * (double)aj; Qd -= w * (double)s_b[j]; }
        // aj == 0: threshold is +INF, never crossed; value unchanged
        bl->PQ[k * NSEG + s] = make_float2((float)Pd, (float)Qd);
    }

    // W3 transposed so (W3[0][u],W3[1][u],W3[2][u],W3[3][u]) is one LDS.128
    for (int q = 0; q < 4; ++q) bl->w3t[k * 4 + q] = W3[f * 256 + q * 64 + k];
    if (k < 4) bl->b3[k] = b3[f * 4 + k];
    if (k < 9) bl->wc[k] = g_pre.Wc[f][k];
    if (k < 3) bl->c[k]  = g_pre.c[f][k];
}

// ---------------------------------------------------------------------------
// Main kernel: 256 threads/CTA, 2 samples/thread -> grid fits in ONE wave.
// ---------------------------------------------------------------------------
__global__ __launch_bounds__(256, 4)
void glow_main(const float* __restrict__ eps, float* __restrict__ out, int N) {
    extern __shared__ float4 sm4[];
    FlowBlob* sb = (FlowBlob*)sm4;

    const int tid = threadIdx.x;
    const int iA0 = blockIdx.x * 512 + tid;
    const int iB0 = iA0 + 256;
    const bool vA = iA0 < N, vB = iB0 < N;
    const int iA = vA ? iA0 : (N - 1);
    const int iB = vB ? iB0 : (N - 1);

    // z = base_mean + eps @ L^T (L lower triangular)
    float LA[9], bmv[3];
    #pragma unroll
    for (int q = 0; q < 9; q++) LA[q] = g_pre.L[q];
    #pragma unroll
    for (int q = 0; q < 3; q++) bmv[q] = g_pre.bm[q];

    float ea0 = eps[3 * iA], ea1 = eps[3 * iA + 1], ea2 = eps[3 * iA + 2];
    float eb0 = eps[3 * iB], eb1 = eps[3 * iB + 1], eb2 = eps[3 * iB + 2];
    float zA0 = bmv[0] + LA[0] * ea0;
    float zA1 = bmv[1] + LA[3] * ea0 + LA[4] * ea1;
    float zA2 = bmv[2] + LA[6] * ea0 + LA[7] * ea1 + LA[8] * ea2;
    float zB0 = bmv[0] + LA[0] * eb0;
    float zB1 = bmv[1] + LA[3] * eb0 + LA[4] * eb1;
    float zB2 = bmv[2] + LA[6] * eb0 + LA[7] * eb1 + LA[8] * eb2;
    float ldA = 0.f, ldB = 0.f;

    for (int f = 0; f < NFLOWS; ++f) {
        __syncthreads();  // protect smem from previous flow's readers
        {   // stage this flow's blob (34624 B) via float4
            const float4* src = (const float4*)&g_blob[f];
            #pragma unroll
            for (int t = tid; t < (int)BLOB_F4; t += 256) sm4[t] = src[t];
        }
        __syncthreads();

        // ---- folded actnorm + 1x1 conv: z <- Wc z + c ----
        {
            float w0 = sb->wc[0], w1 = sb->wc[1], w2 = sb->wc[2];
            float w3 = sb->wc[3], w4 = sb->wc[4], w5 = sb->wc[5];
            float w6 = sb->wc[6], w7 = sb->wc[7], w8 = sb->wc[8];
            float c0 = sb->c[0], c1 = sb->c[1], c2 = sb->c[2];
            float nA0 = c0 + w0 * zA0 + w1 * zA1 + w2 * zA2;
            float nA1 = c1 + w3 * zA0 + w4 * zA1 + w5 * zA2;
            float nA2 = c2 + w6 * zA0 + w7 * zA1 + w8 * zA2;
            float nB0 = c0 + w0 * zB0 + w1 * zB1 + w2 * zB2;
            float nB1 = c1 + w3 * zB0 + w4 * zB1 + w5 * zB2;
            float nB2 = c2 + w6 * zB0 + w7 * zB1 + w8 * zB2;
            zA0 = nA0; zA1 = nA1; zA2 = nA2;
            zB0 = nB0; zB1 = nB1; zB2 = nB2;
        }

        // ---- segment lookup: s = #{thr < x}, branchless binary search ----
        const float* thr = sb->thr;
        int sA = 0, sB = 0;
        #pragma unroll
        for (int st = 32; st >= 1; st >>= 1) {
            if (thr[sA + st - 1] < zA0) sA += st;
            if (thr[sB + st - 1] < zB0) sB += st;
        }

        // ---- MLP via piecewise-linear table ----
        u64 a01A = *(const u64*)&sb->b3[0];
        u64 a23A = *(const u64*)&sb->b3[2];
        u64 a01B = a01A, a23B = a23A;

        const float2* pqA = sb->PQ + sA;
        const float2* pqB = sb->PQ + sB;
        const ulonglong2* w3u = (const ulonglong2*)sb->w3t;

        #pragma unroll 8
        for (int u = 0; u < 64; ++u) {
            ulonglong2 w = w3u[u];                      // broadcast LDS.128
            float2 pa = pqA[u * NSEG];                  // LDS.64 gather
            float ga = fmaxf(fmaf(pa.x, zA0, pa.y), 0.f);
            u64 gga = pk2(ga, ga);
            a01A = fma2(gga, w.x, a01A);
            a23A = fma2(gga, w.y, a23A);
            float2 pb = pqB[u * NSEG];
            float gb = fmaxf(fmaf(pb.x, zB0, pb.y), 0.f);
            u64 ggb = pk2(gb, gb);
            a01B = fma2(ggb, w.x, a01B);
            a23B = fma2(ggb, w.y, a23B);
        }

        // ---- affine coupling on dims 1,2 ----
        {
            float o0, o1, o2, o3;
            upk2(a01A, o0, o1); upk2(a23A, o2, o3);
            zA1 = fmaf(zA1, __expf(o2), o0);
            zA2 = fmaf(zA2, __expf(o3), o1);
            ldA += o2 + o3;
            upk2(a01B, o0, o1); upk2(a23B, o2, o3);
            zB1 = fmaf(zB1, __expf(o2), o0);
            zB2 = fmaf(zB2, __expf(o3), o1);
            ldB += o2 + o3;
        }
    }

    float totc = g_pre.totc;
    if (vA) {
        out[3 * iA]     = zA0;
        out[3 * iA + 1] = __expf(zA1);
        out[3 * iA + 2] = __expf(zA2);
        out[3 * N + iA] = ldA + totc + zA1 + zA2;
    }
    if (vB) {
        out[3 * iB]     = zB0;
        out[3 * iB + 1] = __expf(zB1);
        out[3 * iB + 2] = __expf(zB2);
        out[3 * N + iB] = ldB + totc + zB1 + zB2;
    }
}

// ---------------------------------------------------------------------------
// Launch. Inputs (metadata order): eps, L_tril, base_mean, an_log_scale,
// an_shift, perm_p, sign_s, lu_l, lu_u, lu_log_s, W1, b1, W2, b2, W3, b3
// Output: [z_t (N,3) row-major][log_det (N)] float32 (layout verified R4)
// ---------------------------------------------------------------------------
extern "C" void kernel_launch(void* const* d_in, const int* in_sizes, int n_in,
                              void* d_out, int out_size) {
    const float* eps    = (const float*)d_in[0];
    const float* L_tril = (const float*)d_in[1];
    const float* bm     = (const float*)d_in[2];
    const float* an_ls  = (const float*)d_in[3];
    const float* an_sh  = (const float*)d_in[4];
    const float* perm   = (const float*)d_in[5];
    const float* ss     = (const float*)d_in[6];
    const float* lu_l   = (const float*)d_in[7];
    const float* lu_u   = (const float*)d_in[8];
    const float* lu_ls  = (const float*)d_in[9];
    const float* W1     = (const float*)d_in[10];
    const float* b1     = (const float*)d_in[11];
    const float* W2     = (const float*)d_in[12];
    const float* b2     = (const float*)d_in[13];
    const float* W3     = (const float*)d_in[14];
    const float* b3     = (const float*)d_in[15];
    float* out = (float*)d_out;

    int N = in_sizes[0] / 3;

    prep_math<<<1, 32>>>(L_tril, bm, an_ls, an_sh, perm, ss, lu_l, lu_u, lu_ls);
    prep_build<<<NFLOWS, 64>>>(W1, b1, W2, b2, W3, b3);

    int blocks = (N + 511) / 512;
    glow_main<<<blocks, 256, sizeof(FlowBlob)>>>(eps, out, N);
}